// round 3
// baseline (speedup 1.0000x reference)
#include <cuda_runtime.h>
#include <cuda_bf16.h>

// BilateralBlur: fused separable depth-guided blur + contrast blend.
// Tile: 32x32 outputs per CTA, 36x36 halo staged in SMEM.

#define TW 32
#define TH 32
#define HW 36  // TW + 2*R
#define HH 36  // TH + 2*R

__global__ __launch_bounds__(256, 4)
void bilateral_blur_kernel(const float* __restrict__ bright,
                           const float* __restrict__ dark,
                           const float* __restrict__ depths,
                           const float* __restrict__ p_dv,
                           const float* __restrict__ p_sv,
                           const float* __restrict__ p_dexp,
                           const float* __restrict__ p_deps,
                           const float* __restrict__ p_ce,
                           float* __restrict__ out,
                           int H, int W)
{
    __shared__ float sb[HH][HW];
    __shared__ float sd[HH][HW];
    __shared__ float sz[HH][HW];
    __shared__ float hbx[HH][TW];   // horizontally-blurred bright
    __shared__ float hdx[HH][TW];   // horizontally-blurred dark

    const int tid = threadIdx.x;
    const int x0 = blockIdx.x * TW;
    const int y0 = blockIdx.y * TH;
    const long long base = (long long)blockIdx.z * (long long)H * (long long)W;

    const float dv   = *p_dv;
    const float sv   = *p_sv;
    const float dexp = *p_dexp;
    const float deps = *p_deps;
    const float ce   = *p_ce;
    const float inv2dv = 1.0f / (2.0f * dv);
    const float inv2sv = 1.0f / (2.0f * sv);

    // precomputed spatial Gaussian taps exp(-i^2/(2*sv)), i = -2..2
    float sw[5];
    #pragma unroll
    for (int j = 0; j < 5; j++) {
        float d = (float)(j - 2);
        sw[j] = __expf(-d * d * inv2sv);
    }

    // ---- stage input tiles (zero-padded halo, matches reference zero padding) ----
    for (int idx = tid; idx < HH * HW; idx += 256) {
        int r = idx / HW, c = idx % HW;
        int y = y0 + r - 2;
        int x = x0 + c - 2;
        float b = 0.0f, d = 0.0f, z = 0.0f;
        if ((unsigned)y < (unsigned)H && (unsigned)x < (unsigned)W) {
            long long g = base + (long long)y * W + x;
            b = bright[g];
            d = dark[g];
            z = depths[g];
        }
        sb[r][c] = b; sd[r][c] = d; sz[r][c] = z;
    }
    __syncthreads();

    // ---- horizontal pass: all 36 rows x 32 output cols ----
    for (int idx = tid; idx < HH * TW; idx += 256) {
        int r = idx / TW, c = idx % TW;
        int y = y0 + r - 2;
        float bx = 0.0f, dx = 0.0f;
        if ((unsigned)y < (unsigned)H) {           // OOB rows stay exactly 0 (reference zero-pads bright_x)
            float zc  = sz[r][c + 2];
            float inv = __frcp_rn(zc);
            float wsum = 0.0f, bs = 0.0f, ds = 0.0f;
            #pragma unroll
            for (int j = 0; j < 5; j++) {
                float zp  = sz[r][c + j];
                float rel = fminf(fabsf(zp * inv - 1.0f), 1.0f); // OOB tap: zp=0 -> rel=1 -> w underflows to 0
                float w   = __expf(-rel * rel * inv2dv) * sw[j];
                wsum += w;
                bs   += sb[r][c + j] * w;
                ds   += sd[r][c + j] * w;
            }
            float invw = __frcp_rn(wsum);          // center tap guarantees wsum >= sw[2] > 0
            bx = bs * invw;
            dx = ds * invw;
        }
        hbx[r][c] = bx;
        hdx[r][c] = dx;
    }
    __syncthreads();

    // ---- vertical pass + contrast blend: 32x32 outputs ----
    for (int idx = tid; idx < TH * TW; idx += 256) {
        int r = idx / TW, c = idx % TW;
        int y = y0 + r, x = x0 + c;
        if (y >= H || x >= W) continue;

        float zc  = sz[r + 2][c + 2];
        float inv = __frcp_rn(zc);
        float wsum = 0.0f, bs = 0.0f, ds = 0.0f;
        #pragma unroll
        for (int j = 0; j < 5; j++) {
            float zp  = sz[r + j][c + 2];
            float rel = fminf(fabsf(zp * inv - 1.0f), 1.0f);
            float w   = __expf(-rel * rel * inv2dv) * sw[j];
            wsum += w;
            bs   += hbx[r + j][c] * w;
            ds   += hdx[r + j][c] * w;
        }
        float invw  = __frcp_rn(wsum);
        float bmean = bs * invw;
        float dmean = ds * invw;

        float bcen = sb[r + 2][c + 2];
        float dcen = sd[r + 2][c + 2];

        // custom_pow(a, e) = exp(e * log(max(a, 1e-8)))
        float devb = __expf(dexp * __logf(fmaxf(fabsf(bcen - bmean), 1e-8f))) * ce;
        float devd = fmaxf(__expf(dexp * __logf(fmaxf(fabsf(dcen - dmean), 1e-8f))), deps);
        float invs = __frcp_rn(devb + devd);

        out[base + (long long)y * W + x] = (devd * bcen + devb * dcen) * invs;
    }
}

extern "C" void kernel_launch(void* const* d_in, const int* in_sizes, int n_in,
                              void* d_out, int out_size)
{
    const float* bright = (const float*)d_in[0];
    const float* dark   = (const float*)d_in[1];
    const float* depths = (const float*)d_in[2];
    const float* dv     = (const float*)d_in[3];
    const float* sv     = (const float*)d_in[4];
    const float* dexp   = (const float*)d_in[5];
    const float* deps   = (const float*)d_in[6];
    const float* ce     = (const float*)d_in[7];
    float* out = (float*)d_out;

    const int H = 1024, W = 1024;
    const int B = in_sizes[0] / (H * W);

    dim3 grid((W + TW - 1) / TW, (H + TH - 1) / TH, B);
    bilateral_blur_kernel<<<grid, 256>>>(bright, dark, depths,
                                         dv, sv, dexp, deps, ce,
                                         out, H, W);
}

// round 4
// speedup vs baseline: 1.1128x; 1.1128x over previous
#include <cuda_runtime.h>
#include <cuda_bf16.h>

// BilateralBlur v2: fused separable depth-guided blur + contrast blend.
// float2-vectorized: each thread owns 2 adjacent x pixels. Tile 64x32, halo 72x36.
// Block (32,8) = 256 threads; no div/mod in hot phases; all SMEM ops are .64.

#define RAD 2
#define TW 64          // output tile width
#define TH 32          // output tile height
#define SW 72          // staged width  (x0-4 .. x0+67; taps need x0-2..x0+65)
#define SH 36          // staged height (y0-2 .. y0+33)
#define NT 256

__global__ __launch_bounds__(NT, 4)
void bilateral_blur_v2(const float* __restrict__ bright,
                       const float* __restrict__ dark,
                       const float* __restrict__ depths,
                       const float* __restrict__ p_dv,
                       const float* __restrict__ p_sv,
                       const float* __restrict__ p_dexp,
                       const float* __restrict__ p_deps,
                       const float* __restrict__ p_ce,
                       float* __restrict__ out,
                       int H, int W)
{
    __shared__ float sb[SH][SW];
    __shared__ float sd[SH][SW];
    __shared__ float sz[SH][SW];
    __shared__ float hb[SH][TW];
    __shared__ float hd[SH][TW];

    const int tx = threadIdx.x;          // 0..31
    const int ty = threadIdx.y;          // 0..7
    const int tid = ty * 32 + tx;
    const int x0 = blockIdx.x * TW;
    const int y0 = blockIdx.y * TH;
    const size_t base = (size_t)blockIdx.z * (size_t)H * (size_t)W;

    const float inv2dv = 0.5f / *p_dv;
    const float inv2sv = 0.5f / *p_sv;
    const float dexp = *p_dexp;
    const float deps = *p_deps;
    const float ce   = *p_ce;

    // spatial Gaussian taps exp(-i^2/(2*sv)), i = -2..2
    const float g1 = __expf(-inv2sv);
    const float g2 = __expf(-4.0f * inv2sv);
    const float swt[5] = { g2, g1, 1.0f, g1, g2 };

    // ---- stage 36 rows x 36 float2 of bright/dark/depths (zero-padded halo) ----
    for (int idx = tid; idx < SH * (SW / 2); idx += NT) {
        int r  = idx / (SW / 2);
        int c2 = idx - r * (SW / 2);
        int y  = y0 + r - RAD;
        int x  = x0 + 2 * c2 - 4;         // even; an OOB float2 is entirely OOB
        float2 b = make_float2(0.f, 0.f);
        float2 d = make_float2(0.f, 0.f);
        float2 z = make_float2(0.f, 0.f);
        if ((unsigned)y < (unsigned)H && (unsigned)x < (unsigned)W) {
            size_t g = base + (size_t)y * W + x;
            b = *(const float2*)(bright + g);
            d = *(const float2*)(dark + g);
            z = *(const float2*)(depths + g);
        }
        *(float2*)&sb[r][2 * c2] = b;
        *(float2*)&sd[r][2 * c2] = d;
        *(float2*)&sz[r][2 * c2] = z;
    }
    __syncthreads();

    const int c = 2 * tx;                 // local output col (even, 0..62)

    // ---- horizontal pass: 36 halo rows, 8 rows per sweep ----
    for (int r = ty; r < SH; r += 8) {
        float2 rb = make_float2(0.f, 0.f);
        float2 rd = make_float2(0.f, 0.f);
        int y = y0 + r - RAD;
        if ((unsigned)y < (unsigned)H) {  // OOB rows stay 0 (reference zero-pads bright_x)
            // taps c-2..c+3 in output coords -> staged cols c+2..c+7 (aligned float2 x3)
            float2 z01 = *(const float2*)&sz[r][c + 2];
            float2 z23 = *(const float2*)&sz[r][c + 4];
            float2 z45 = *(const float2*)&sz[r][c + 6];
            float2 b01 = *(const float2*)&sb[r][c + 2];
            float2 b23 = *(const float2*)&sb[r][c + 4];
            float2 b45 = *(const float2*)&sb[r][c + 6];
            float2 d01 = *(const float2*)&sd[r][c + 2];
            float2 d23 = *(const float2*)&sd[r][c + 4];
            float2 d45 = *(const float2*)&sd[r][c + 6];
            float zt[6] = { z01.x, z01.y, z23.x, z23.y, z45.x, z45.y };
            float bt[6] = { b01.x, b01.y, b23.x, b23.y, b45.x, b45.y };
            float dt[6] = { d01.x, d01.y, d23.x, d23.y, d45.x, d45.y };
            float inv0 = __frcp_rn(zt[2]);
            float inv1 = __frcp_rn(zt[3]);
            float ws0 = 0.f, bs0 = 0.f, ds0 = 0.f;
            float ws1 = 0.f, bs1 = 0.f, ds1 = 0.f;
            #pragma unroll
            for (int j = 0; j < 5; j++) {
                float rel0 = fminf(fabsf(zt[j] * inv0 - 1.f), 1.f);     // OOB tap: z=0 -> rel=1 -> w underflows to 0
                float w0 = __expf(-rel0 * rel0 * inv2dv) * swt[j];
                ws0 += w0; bs0 = fmaf(bt[j], w0, bs0); ds0 = fmaf(dt[j], w0, ds0);
                float rel1 = fminf(fabsf(zt[j + 1] * inv1 - 1.f), 1.f);
                float w1 = __expf(-rel1 * rel1 * inv2dv) * swt[j];
                ws1 += w1; bs1 = fmaf(bt[j + 1], w1, bs1); ds1 = fmaf(dt[j + 1], w1, ds1);
            }
            float iw0 = __frcp_rn(ws0);   // center tap guarantees ws > 0
            float iw1 = __frcp_rn(ws1);
            rb = make_float2(bs0 * iw0, bs1 * iw1);
            rd = make_float2(ds0 * iw0, ds1 * iw1);
        }
        *(float2*)&hb[r][c] = rb;
        *(float2*)&hd[r][c] = rd;
    }
    __syncthreads();

    // ---- vertical pass + contrast blend: 32 rows, 8 per sweep ----
    for (int r = ty; r < TH; r += 8) {
        float2 zc = *(const float2*)&sz[r + 2][c + 4];
        float inv0 = __frcp_rn(zc.x);
        float inv1 = __frcp_rn(zc.y);
        float ws0 = 0.f, bs0 = 0.f, ds0 = 0.f;
        float ws1 = 0.f, bs1 = 0.f, ds1 = 0.f;
        #pragma unroll
        for (int j = 0; j < 5; j++) {
            float2 zp  = *(const float2*)&sz[r + j][c + 4];
            float2 hbp = *(const float2*)&hb[r + j][c];
            float2 hdp = *(const float2*)&hd[r + j][c];
            float rel0 = fminf(fabsf(zp.x * inv0 - 1.f), 1.f);
            float w0 = __expf(-rel0 * rel0 * inv2dv) * swt[j];
            ws0 += w0; bs0 = fmaf(hbp.x, w0, bs0); ds0 = fmaf(hdp.x, w0, ds0);
            float rel1 = fminf(fabsf(zp.y * inv1 - 1.f), 1.f);
            float w1 = __expf(-rel1 * rel1 * inv2dv) * swt[j];
            ws1 += w1; bs1 = fmaf(hbp.y, w1, bs1); ds1 = fmaf(hdp.y, w1, ds1);
        }
        float iw0 = __frcp_rn(ws0);
        float iw1 = __frcp_rn(ws1);
        float bm0 = bs0 * iw0, dm0 = ds0 * iw0;
        float bm1 = bs1 * iw1, dm1 = ds1 * iw1;

        float2 bc = *(const float2*)&sb[r + 2][c + 4];
        float2 dc = *(const float2*)&sd[r + 2][c + 4];

        // custom_pow(a, e) = exp(e * log(max(a, 1e-8)))
        float devb0 = __expf(dexp * __logf(fmaxf(fabsf(bc.x - bm0), 1e-8f))) * ce;
        float devd0 = fmaxf(__expf(dexp * __logf(fmaxf(fabsf(dc.x - dm0), 1e-8f))), deps);
        float o0 = (devd0 * bc.x + devb0 * dc.x) * __frcp_rn(devb0 + devd0);

        float devb1 = __expf(dexp * __logf(fmaxf(fabsf(bc.y - bm1), 1e-8f))) * ce;
        float devd1 = fmaxf(__expf(dexp * __logf(fmaxf(fabsf(dc.y - dm1), 1e-8f))), deps);
        float o1 = (devd1 * bc.y + devb1 * dc.y) * __frcp_rn(devb1 + devd1);

        int y = y0 + r;
        int x = x0 + c;
        if (y < H && x + 1 < W) {
            *(float2*)(out + base + (size_t)y * W + x) = make_float2(o0, o1);
        } else if (y < H && x < W) {
            out[base + (size_t)y * W + x] = o0;
        }
    }
}

extern "C" void kernel_launch(void* const* d_in, const int* in_sizes, int n_in,
                              void* d_out, int out_size)
{
    const float* bright = (const float*)d_in[0];
    const float* dark   = (const float*)d_in[1];
    const float* depths = (const float*)d_in[2];
    const float* dv     = (const float*)d_in[3];
    const float* sv     = (const float*)d_in[4];
    const float* dexp   = (const float*)d_in[5];
    const float* deps   = (const float*)d_in[6];
    const float* ce     = (const float*)d_in[7];
    float* out = (float*)d_out;

    const int H = 1024, W = 1024;
    const int B = in_sizes[0] / (H * W);

    dim3 block(32, 8, 1);
    dim3 grid((W + TW - 1) / TW, (H + TH - 1) / TH, B);
    bilateral_blur_v2<<<grid, block>>>(bright, dark, depths,
                                       dv, sv, dexp, deps, ce,
                                       out, H, W);
}

// round 7
// speedup vs baseline: 1.3102x; 1.1774x over previous
#include <cuda_runtime.h>
#include <cuda_bf16.h>

// BilateralBlur v3: register-resident sliding-window, zero shared memory.
// One warp = 64-wide x 64-tall strip (2 px/thread). Horizontal taps via warp
// shuffles; vertical taps via a 5-row register ring rotated by 5x unroll.

#define LOG2E 1.4426950408889634f
#define FULLM 0xffffffffu

__device__ __forceinline__ float ex2a(float x){ float r; asm("ex2.approx.ftz.f32 %0, %1;" : "=f"(r) : "f"(x)); return r; }
__device__ __forceinline__ float lg2a(float x){ float r; asm("lg2.approx.ftz.f32 %0, %1;" : "=f"(r) : "f"(x)); return r; }
__device__ __forceinline__ float rcpa(float x){ float r; asm("rcp.approx.ftz.f32 %0, %1;" : "=f"(r) : "f"(x)); return r; }
__device__ __forceinline__ float2 zero2(){ return make_float2(0.f, 0.f); }

struct Slot { float2 z, hb, hd, b, d; };

// horizontal 5-tap depth-guided blur for 2 adjacent pixels
__device__ __forceinline__ void hblur(const float2 Lz, const float2 z, const float2 Rz,
                                      const float2 Lb, const float2 b, const float2 Rb,
                                      const float2 Ld, const float2 d, const float2 Rd,
                                      const float K2, const float* __restrict__ lsw,
                                      float2& hb, float2& hd)
{
    float zt[6] = { Lz.x, Lz.y, z.x, z.y, Rz.x, Rz.y };
    float bt[6] = { Lb.x, Lb.y, b.x, b.y, Rb.x, Rb.y };
    float dt[6] = { Ld.x, Ld.y, d.x, d.y, Rd.x, Rd.y };
    float i0 = rcpa(zt[2]);
    float i1 = rcpa(zt[3]);
    float ws0 = 0.f, bs0 = 0.f, ds0 = 0.f;
    float ws1 = 0.f, bs1 = 0.f, ds1 = 0.f;
    #pragma unroll
    for (int j = 0; j < 5; j++) {
        float t0 = fminf(fabsf(fmaf(zt[j], i0, -1.f)), 1.f);      // OOB tap: z=0 -> t=1 -> w underflows to 0
        float w0 = ex2a(fmaf(t0 * t0, K2, lsw[j]));
        ws0 += w0; bs0 = fmaf(bt[j], w0, bs0); ds0 = fmaf(dt[j], w0, ds0);
        float t1 = fminf(fabsf(fmaf(zt[j + 1], i1, -1.f)), 1.f);
        float w1 = ex2a(fmaf(t1 * t1, K2, lsw[j]));
        ws1 += w1; bs1 = fmaf(bt[j + 1], w1, bs1); ds1 = fmaf(dt[j + 1], w1, ds1);
    }
    float n0 = rcpa(ws0);                                          // center tap keeps ws > 0
    float n1 = rcpa(ws1);
    hb = make_float2(bs0 * n0, bs1 * n1);
    hd = make_float2(ds0 * n0, ds1 * n1);
}

// vertical 5-tap blur (rows A..E, center C) + contrast blend epilogue
__device__ __forceinline__ float2 vblend(const Slot& A, const Slot& B, const Slot& C,
                                         const Slot& D, const Slot& E,
                                         const float K2, const float* __restrict__ lsw,
                                         const float dexp, const float deps, const float ce)
{
    float i0 = rcpa(C.z.x);
    float i1 = rcpa(C.z.y);
    float ws0 = 0.f, bs0 = 0.f, ds0 = 0.f;
    float ws1 = 0.f, bs1 = 0.f, ds1 = 0.f;
    #define VTAP(S, J) { \
        float t0 = fminf(fabsf(fmaf((S).z.x, i0, -1.f)), 1.f); \
        float w0 = ex2a(fmaf(t0 * t0, K2, lsw[J])); \
        ws0 += w0; bs0 = fmaf((S).hb.x, w0, bs0); ds0 = fmaf((S).hd.x, w0, ds0); \
        float t1 = fminf(fabsf(fmaf((S).z.y, i1, -1.f)), 1.f); \
        float w1 = ex2a(fmaf(t1 * t1, K2, lsw[J])); \
        ws1 += w1; bs1 = fmaf((S).hb.y, w1, bs1); ds1 = fmaf((S).hd.y, w1, ds1); }
    VTAP(A, 0) VTAP(B, 1) VTAP(C, 2) VTAP(D, 3) VTAP(E, 4)
    #undef VTAP
    float n0 = rcpa(ws0), n1 = rcpa(ws1);
    float bm0 = bs0 * n0, dm0 = ds0 * n0;
    float bm1 = bs1 * n1, dm1 = ds1 * n1;

    // custom_pow(a,e) = a^e = ex2(e * lg2(max(a,1e-8)))
    float devb0 = ex2a(dexp * lg2a(fmaxf(fabsf(C.b.x - bm0), 1e-8f))) * ce;
    float devd0 = fmaxf(ex2a(dexp * lg2a(fmaxf(fabsf(C.d.x - dm0), 1e-8f))), deps);
    float o0 = (devd0 * C.b.x + devb0 * C.d.x) * rcpa(devb0 + devd0);

    float devb1 = ex2a(dexp * lg2a(fmaxf(fabsf(C.b.y - bm1), 1e-8f))) * ce;
    float devd1 = fmaxf(ex2a(dexp * lg2a(fmaxf(fabsf(C.d.y - dm1), 1e-8f))), deps);
    float o1 = (devd1 * C.b.y + devb1 * C.d.y) * rcpa(devb1 + devd1);
    return make_float2(o0, o1);
}

__global__ __launch_bounds__(128)
void bilateral_blur_v3(const float* __restrict__ bright,
                       const float* __restrict__ dark,
                       const float* __restrict__ depths,
                       const float* __restrict__ p_dv,
                       const float* __restrict__ p_sv,
                       const float* __restrict__ p_dexp,
                       const float* __restrict__ p_deps,
                       const float* __restrict__ p_ce,
                       float* __restrict__ out,
                       int H, int W)
{
    const int lane = threadIdx.x & 31;
    const int warp = threadIdx.x >> 5;
    const int xs = blockIdx.x * 64;               // strip start column
    const int x  = xs + lane * 2;                 // this thread's 2 pixels
    const int chunk = blockIdx.y * 4 + warp;      // 64-row chunk id
    const int ys = chunk * 64;
    const size_t base = (size_t)blockIdx.z * (size_t)H * (size_t)W;

    const float inv2dv = 0.5f / *p_dv;
    const float inv2sv = 0.5f / *p_sv;
    const float dexp = *p_dexp;
    const float deps = *p_deps;
    const float ce   = *p_ce;
    const float K2 = -inv2dv * LOG2E;             // w = ex2(rel^2*K2 + lsw[j])
    float lsw[5];
    #pragma unroll
    for (int j = 0; j < 5; j++) {
        float dd = (float)(j - 2);
        lsw[j] = -dd * dd * inv2sv * LOG2E;
    }

    const float* pb = bright + base + x;
    const float* pd = dark   + base + x;
    const float* pz = depths + base + x;
    const float* lb = bright + base + xs - 2;     // left halo (deref'd only if xs>0)
    const float* ld = dark   + base + xs - 2;
    const float* lz = depths + base + xs - 2;
    const float* rb = bright + base + xs + 64;    // right halo (deref'd only if xs+64<W)
    const float* rd = dark   + base + xs + 64;
    const float* rz = depths + base + xs + 64;
    float* po = out + base + x;

    const int ylim = (ys + 66 < H) ? (ys + 66) : H;  // rows ys-2 .. ys+65
    const bool haloL = (xs > 0);
    const bool haloR = (xs + 64 < W);

    int y = ys - 2;
    long long rowoff = (long long)y * W;

    Slot s0, s1, s2, s3, s4;
    s0.z = s1.z = s2.z = s3.z = s4.z = zero2();
    s0.hb = s1.hb = s2.hb = s3.hb = s4.hb = zero2();
    s0.hd = s1.hd = s2.hd = s3.hd = s4.hd = zero2();
    s0.b = s1.b = s2.b = s3.b = s4.b = zero2();
    s0.d = s1.d = s2.d = s3.d = s4.d = zero2();

#define STEP(W0, W1, W2, W3, W4) do { \
    float2 b = zero2(), d = zero2(), z = zero2(); \
    float2 hb = zero2(), hd = zero2(); \
    const bool rv = ((unsigned)y < (unsigned)ylim); \
    if (rv) { \
        b = *(const float2*)(pb + rowoff); \
        d = *(const float2*)(pd + rowoff); \
        z = *(const float2*)(pz + rowoff); \
        float2 eLb = zero2(), eLd = zero2(), eLz = zero2(); \
        float2 eRb = zero2(), eRd = zero2(), eRz = zero2(); \
        if (lane == 0 && haloL) { \
            eLb = *(const float2*)(lb + rowoff); \
            eLd = *(const float2*)(ld + rowoff); \
            eLz = *(const float2*)(lz + rowoff); \
        } \
        if (lane == 31 && haloR) { \
            eRb = *(const float2*)(rb + rowoff); \
            eRd = *(const float2*)(rd + rowoff); \
            eRz = *(const float2*)(rz + rowoff); \
        } \
        float2 Lb, Ld, Lz, Rb, Rd, Rz; \
        Lb.x = __shfl_up_sync(FULLM, b.x, 1);  Lb.y = __shfl_up_sync(FULLM, b.y, 1); \
        Ld.x = __shfl_up_sync(FULLM, d.x, 1);  Ld.y = __shfl_up_sync(FULLM, d.y, 1); \
        Lz.x = __shfl_up_sync(FULLM, z.x, 1);  Lz.y = __shfl_up_sync(FULLM, z.y, 1); \
        Rb.x = __shfl_down_sync(FULLM, b.x, 1); Rb.y = __shfl_down_sync(FULLM, b.y, 1); \
        Rd.x = __shfl_down_sync(FULLM, d.x, 1); Rd.y = __shfl_down_sync(FULLM, d.y, 1); \
        Rz.x = __shfl_down_sync(FULLM, z.x, 1); Rz.y = __shfl_down_sync(FULLM, z.y, 1); \
        if (lane == 0)  { Lb = eLb; Ld = eLd; Lz = eLz; } \
        if (lane == 31) { Rb = eRb; Rd = eRd; Rz = eRz; } \
        hblur(Lz, z, Rz, Lb, b, Rb, Ld, d, Rd, K2, lsw, hb, hd); \
    } \
    W4.z = z; W4.hb = hb; W4.hd = hd; W4.b = b; W4.d = d; \
    if ((unsigned)(y - (ys + 2)) < 64u) { \
        float2 o = vblend(W0, W1, W2, W3, W4, K2, lsw, dexp, deps, ce); \
        *(float2*)(po + rowoff - 2 * W) = o; \
    } \
    y++; rowoff += W; \
} while (0)

    // 70 iterations (rows ys-2 .. ys+67; last 2 and any OOB are no-ops)
    for (int it = 0; it < 14; ++it) {
        STEP(s1, s2, s3, s4, s0);
        STEP(s2, s3, s4, s0, s1);
        STEP(s3, s4, s0, s1, s2);
        STEP(s4, s0, s1, s2, s3);
        STEP(s0, s1, s2, s3, s4);
    }
#undef STEP
}

extern "C" void kernel_launch(void* const* d_in, const int* in_sizes, int n_in,
                              void* d_out, int out_size)
{
    const float* bright = (const float*)d_in[0];
    const float* dark   = (const float*)d_in[1];
    const float* depths = (const float*)d_in[2];
    const float* dv     = (const float*)d_in[3];
    const float* sv     = (const float*)d_in[4];
    const float* dexp   = (const float*)d_in[5];
    const float* deps   = (const float*)d_in[6];
    const float* ce     = (const float*)d_in[7];
    float* out = (float*)d_out;

    const int H = 1024, W = 1024;
    const int B = in_sizes[0] / (H * W);

    dim3 block(128, 1, 1);
    dim3 grid(W / 64, (H / 64) / 4, B);   // 16 x 4 x B blocks, 4 warps each
    bilateral_blur_v3<<<grid, block>>>(bright, dark, depths,
                                       dv, sv, dexp, deps, ce,
                                       out, H, W);
}

// round 9
// speedup vs baseline: 1.3409x; 1.0234x over previous
#include <cuda_runtime.h>
#include <cuda_bf16.h>

// BilateralBlur v4b: register-resident sliding window, 1 px/thread.
// Warp = 32-wide x 32-row chunk. Horizontal taps via 4 shuffles/array +
// scalar edge-lane halo loads (alignment-safe); vertical taps via 5-row
// register ring (5x unroll). Zero shared memory, zero barriers.

#define LOG2E 1.4426950408889634f
#define FULLM 0xffffffffu

__device__ __forceinline__ float ex2a(float x){ float r; asm("ex2.approx.ftz.f32 %0, %1;" : "=f"(r) : "f"(x)); return r; }
__device__ __forceinline__ float lg2a(float x){ float r; asm("lg2.approx.ftz.f32 %0, %1;" : "=f"(r) : "f"(x)); return r; }
__device__ __forceinline__ float rcpa(float x){ float r; asm("rcp.approx.ftz.f32 %0, %1;" : "=f"(r) : "f"(x)); return r; }

struct Slot { float z, hb, hd, b, d; };

__global__ __launch_bounds__(128, 7)
void bilateral_blur_v4(const float* __restrict__ bright,
                       const float* __restrict__ dark,
                       const float* __restrict__ depths,
                       const float* __restrict__ p_dv,
                       const float* __restrict__ p_sv,
                       const float* __restrict__ p_dexp,
                       const float* __restrict__ p_deps,
                       const float* __restrict__ p_ce,
                       float* __restrict__ out,
                       int H, int W)
{
    const int lane = threadIdx.x & 31;
    const int warp = threadIdx.x >> 5;
    const int xs = blockIdx.x * 32;                // strip start column
    const int x  = xs + lane;                      // this thread's pixel column
    const int ys = (blockIdx.y * 4 + warp) * 32;   // 32-row chunk start
    const size_t base = (size_t)blockIdx.z * (size_t)H * (size_t)W;

    const float inv2dv = 0.5f / *p_dv;
    const float inv2sv = 0.5f / *p_sv;
    const float dexp = *p_dexp;
    const float deps = *p_deps;
    const float ce   = *p_ce;
    const float K2 = -inv2dv * LOG2E;              // w = ex2(rel^2*K2 + lsw[j])
    float lsw[5];
    #pragma unroll
    for (int j = 0; j < 5; j++) {
        float dd = (float)(j - 2);
        lsw[j] = -dd * dd * inv2sv * LOG2E;
    }

    const bool haloL = (xs > 0);
    const bool haloR = (xs + 32 < W);
    // per-lane halo-load predicates (scalar loads, always 4B-aligned)
    const bool ldL2 = haloL && (lane < 2);         // needs element x-2
    const bool ldL1 = haloL && (lane == 0);        // needs element x-1
    const bool ldR2 = haloR && (lane >= 30);       // needs element x+2
    const bool ldR1 = haloR && (lane == 31);       // needs element x+1

    const float* pb = bright + base + (ptrdiff_t)(ys - 2) * W + x;
    const float* pd = dark   + base + (ptrdiff_t)(ys - 2) * W + x;
    const float* pz = depths + base + (ptrdiff_t)(ys - 2) * W + x;
    float*       po = out    + base + (ptrdiff_t)(ys - 4) * W + x;

    int y = ys - 2;
    const int ylim = (ys + 34 < H) ? (ys + 34) : H; // load rows ys-2 .. ys+33

    Slot s0, s1, s2, s3, s4;
    s0 = s1 = s2 = s3 = s4 = Slot{0.f, 0.f, 0.f, 0.f, 0.f};

#define STEP(S0, S1, S2, S3, S4) do { \
    float b = 0.f, d = 0.f, z = 0.f, hb = 0.f, hd = 0.f; \
    if ((unsigned)y < (unsigned)ylim) { \
        b = __ldg(pb); d = __ldg(pd); z = __ldg(pz); \
        /* edge halo: scalar loads, zero at the image border (matches zero-pad) */ \
        float ebL2 = 0.f, edL2 = 0.f, ezL2 = 0.f; \
        float ebL1 = 0.f, edL1 = 0.f, ezL1 = 0.f; \
        float ebR2 = 0.f, edR2 = 0.f, ezR2 = 0.f; \
        float ebR1 = 0.f, edR1 = 0.f, ezR1 = 0.f; \
        if (ldL2) { ebL2 = pb[-2]; edL2 = pd[-2]; ezL2 = pz[-2]; } \
        if (ldL1) { ebL1 = pb[-1]; edL1 = pd[-1]; ezL1 = pz[-1]; } \
        if (ldR2) { ebR2 = pb[ 2]; edR2 = pd[ 2]; ezR2 = pz[ 2]; } \
        if (ldR1) { ebR1 = pb[ 1]; edR1 = pd[ 1]; ezR1 = pz[ 1]; } \
        float bL1 = __shfl_up_sync(FULLM, b, 1),   bL2 = __shfl_up_sync(FULLM, b, 2); \
        float bR1 = __shfl_down_sync(FULLM, b, 1), bR2 = __shfl_down_sync(FULLM, b, 2); \
        float dL1 = __shfl_up_sync(FULLM, d, 1),   dL2 = __shfl_up_sync(FULLM, d, 2); \
        float dR1 = __shfl_down_sync(FULLM, d, 1), dR2 = __shfl_down_sync(FULLM, d, 2); \
        float zL1 = __shfl_up_sync(FULLM, z, 1),   zL2 = __shfl_up_sync(FULLM, z, 2); \
        float zR1 = __shfl_down_sync(FULLM, z, 1), zR2 = __shfl_down_sync(FULLM, z, 2); \
        if (lane < 2)   { bL2 = ebL2; dL2 = edL2; zL2 = ezL2; }                 /* zero if !haloL */ \
        if (lane == 0)  { bL1 = ebL1; dL1 = edL1; zL1 = ezL1; } \
        if (lane >= 30) { bR2 = ebR2; dR2 = edR2; zR2 = ezR2; } \
        if (lane == 31) { bR1 = ebR1; dR1 = edR1; zR1 = ezR1; } \
        float zt[5] = { zL2, zL1, z, zR1, zR2 }; \
        float bt[5] = { bL2, bL1, b, bR1, bR2 }; \
        float dt[5] = { dL2, dL1, d, dR1, dR2 }; \
        float zi = rcpa(z); \
        float ws = 0.f, bs = 0.f, ds = 0.f; \
        _Pragma("unroll") \
        for (int j = 0; j < 5; j++) { \
            float t = fminf(fabsf(fmaf(zt[j], zi, -1.f)), 1.f);  /* OOB tap: z=0 -> t=1 -> w underflows to 0 */ \
            float w = ex2a(fmaf(t * t, K2, lsw[j])); \
            ws += w; bs = fmaf(bt[j], w, bs); ds = fmaf(dt[j], w, ds); \
        } \
        float n = rcpa(ws);                   /* center tap keeps ws > 0 */ \
        hb = bs * n; hd = ds * n; \
    } \
    S4.z = z; S4.hb = hb; S4.hd = hd; S4.b = b; S4.d = d; \
    if ((unsigned)(y - ys - 2) < 32u) { \
        float i0 = rcpa(S2.z); \
        float ws = 0.f, bs = 0.f, ds = 0.f; \
        { float t = fminf(fabsf(fmaf(S0.z, i0, -1.f)), 1.f); float w = ex2a(fmaf(t*t, K2, lsw[0])); ws += w; bs = fmaf(S0.hb, w, bs); ds = fmaf(S0.hd, w, ds); } \
        { float t = fminf(fabsf(fmaf(S1.z, i0, -1.f)), 1.f); float w = ex2a(fmaf(t*t, K2, lsw[1])); ws += w; bs = fmaf(S1.hb, w, bs); ds = fmaf(S1.hd, w, ds); } \
        { float t = fminf(fabsf(fmaf(S2.z, i0, -1.f)), 1.f); float w = ex2a(fmaf(t*t, K2, lsw[2])); ws += w; bs = fmaf(S2.hb, w, bs); ds = fmaf(S2.hd, w, ds); } \
        { float t = fminf(fabsf(fmaf(S3.z, i0, -1.f)), 1.f); float w = ex2a(fmaf(t*t, K2, lsw[3])); ws += w; bs = fmaf(S3.hb, w, bs); ds = fmaf(S3.hd, w, ds); } \
        { float t = fminf(fabsf(fmaf(S4.z, i0, -1.f)), 1.f); float w = ex2a(fmaf(t*t, K2, lsw[4])); ws += w; bs = fmaf(S4.hb, w, bs); ds = fmaf(S4.hd, w, ds); } \
        float n = rcpa(ws); \
        float bm = bs * n, dm = ds * n; \
        /* custom_pow(a,e) = ex2(e * lg2(max(a,1e-8))) */ \
        float devb = ex2a(dexp * lg2a(fmaxf(fabsf(S2.b - bm), 1e-8f))) * ce; \
        float devd = fmaxf(ex2a(dexp * lg2a(fmaxf(fabsf(S2.d - dm), 1e-8f))), deps); \
        *po = (devd * S2.b + devb * S2.d) * rcpa(devb + devd); \
    } \
    y++; pb += W; pd += W; pz += W; po += W; \
} while (0)

    // 40 steps: rows ys-2 .. ys+37 (loads stop at ylim, outputs at ys+33; tail no-ops)
    #pragma unroll 1
    for (int it = 0; it < 8; ++it) {
        STEP(s1, s2, s3, s4, s0);
        STEP(s2, s3, s4, s0, s1);
        STEP(s3, s4, s0, s1, s2);
        STEP(s4, s0, s1, s2, s3);
        STEP(s0, s1, s2, s3, s4);
    }
#undef STEP
}

extern "C" void kernel_launch(void* const* d_in, const int* in_sizes, int n_in,
                              void* d_out, int out_size)
{
    const float* bright = (const float*)d_in[0];
    const float* dark   = (const float*)d_in[1];
    const float* depths = (const float*)d_in[2];
    const float* dv     = (const float*)d_in[3];
    const float* sv     = (const float*)d_in[4];
    const float* dexp   = (const float*)d_in[5];
    const float* deps   = (const float*)d_in[6];
    const float* ce     = (const float*)d_in[7];
    float* out = (float*)d_out;

    const int H = 1024, W = 1024;
    const int B = in_sizes[0] / (H * W);

    dim3 block(128, 1, 1);
    dim3 grid(W / 32, (H / 32) / 4, B);   // 32 x 8 x B = 2048 blocks, 4 warps each
    bilateral_blur_v4<<<grid, block>>>(bright, dark, depths,
                                       dv, sv, dexp, deps, ce,
                                       out, H, W);
}